// round 1
// baseline (speedup 1.0000x reference)
#include <cuda_runtime.h>

#define B 64
#define N 16384
#define M 64

// scratch (device globals — no allocation allowed)
__device__ float g_s[B * N];   // logits beta*cos
__device__ float g_wg[B * N];  // gated weights (pre-shift)

// ---------------------------------------------------------------------------
// K1: content addressing logits. Half-warp (16 lanes) per memory row, 4 rows
// per half-warp. lane loads float4 -> contiguous 256B per row, coalesced.
// ---------------------------------------------------------------------------
__global__ __launch_bounds__(256) void k1_logits(
    const float* __restrict__ key,    // [B, M]
    const float* __restrict__ beta,   // [B, 1]
    const float* __restrict__ mem)    // [B, N, M]
{
    const int b    = blockIdx.y;
    const int tid  = threadIdx.x;
    const int hw   = tid >> 4;   // half-warp id in block: 0..15
    const int l    = tid & 15;   // lane within half-warp

    // key float4 for this lane's column slice (reused across all rows)
    const float4 k4 = reinterpret_cast<const float4*>(key + b * M)[l];
    float ks = k4.x * k4.x + k4.y * k4.y + k4.z * k4.z + k4.w * k4.w;

    const int row_base = blockIdx.x * 64;  // 4 iterations * 16 half-warps

    float dot[4], ms[4];
#pragma unroll
    for (int r = 0; r < 4; ++r) {
        const int row = row_base + r * 16 + hw;
        const float4 m4 = reinterpret_cast<const float4*>(
            mem + ((size_t)b * N + row) * M)[l];
        dot[r] = k4.x * m4.x + k4.y * m4.y + k4.z * m4.z + k4.w * m4.w;
        ms[r]  = m4.x * m4.x + m4.y * m4.y + m4.z * m4.z + m4.w * m4.w;
    }

    // width-16 reductions (stay inside the half-warp)
#pragma unroll
    for (int off = 8; off > 0; off >>= 1) {
        ks += __shfl_down_sync(0xFFFFFFFFu, ks, off, 16);
#pragma unroll
        for (int r = 0; r < 4; ++r) {
            dot[r] += __shfl_down_sync(0xFFFFFFFFu, dot[r], off, 16);
            ms[r]  += __shfl_down_sync(0xFFFFFFFFu, ms[r],  off, 16);
        }
    }

    if (l == 0) {
        const float kn = sqrtf(ks);
        const float be = beta[b];
#pragma unroll
        for (int r = 0; r < 4; ++r) {
            const int row = row_base + r * 16 + hw;
            const float denom = fmaxf(kn * sqrtf(ms[r]), 1e-8f);
            g_s[b * N + row] = be * (dot[r] / denom);
        }
    }
}

// ---------------------------------------------------------------------------
// K2: per-batch softmax -> gate -> circular 3-tap shift -> sharpen -> renorm.
// One block per batch, 1024 threads, 16 elements per thread held in registers.
// ---------------------------------------------------------------------------
__global__ __launch_bounds__(1024) void k2_address(
    const float* __restrict__ gate,     // [B,1]
    const float* __restrict__ shift,    // [B,3]
    const float* __restrict__ sharpen,  // [B,1]
    const float* __restrict__ last,     // [B,N]
    float* __restrict__ out)            // [B,N]
{
    const int b   = blockIdx.x;
    const int tid = threadIdx.x;
    const int T   = 1024;
    const int K   = N / T;  // 16

    __shared__ float red[32];
    __shared__ float bc[2];

    const int warp = tid >> 5;
    const int lane = tid & 31;

    float v[K];

    // ---- pass 1: max of logits ----
    float mx = -1e30f;
#pragma unroll
    for (int k = 0; k < K; ++k) {
        v[k] = g_s[b * N + tid + k * T];
        mx = fmaxf(mx, v[k]);
    }
#pragma unroll
    for (int o = 16; o > 0; o >>= 1)
        mx = fmaxf(mx, __shfl_xor_sync(0xFFFFFFFFu, mx, o));
    if (lane == 0) red[warp] = mx;
    __syncthreads();
    if (tid < 32) {
        float x = red[tid];
#pragma unroll
        for (int o = 16; o > 0; o >>= 1)
            x = fmaxf(x, __shfl_xor_sync(0xFFFFFFFFu, x, o));
        if (tid == 0) bc[0] = x;
    }
    __syncthreads();
    mx = bc[0];

    // ---- pass 2: exp + sum ----
    float s = 0.f;
#pragma unroll
    for (int k = 0; k < K; ++k) {
        v[k] = __expf(v[k] - mx);
        s += v[k];
    }
#pragma unroll
    for (int o = 16; o > 0; o >>= 1)
        s += __shfl_xor_sync(0xFFFFFFFFu, s, o);
    if (lane == 0) red[warp] = s;
    __syncthreads();
    if (tid < 32) {
        float x = red[tid];
#pragma unroll
        for (int o = 16; o > 0; o >>= 1)
            x += __shfl_xor_sync(0xFFFFFFFFu, x, o);
        if (tid == 0) bc[1] = x;
    }
    __syncthreads();
    const float inv_sum = 1.0f / bc[1];

    // ---- gate interpolation, stage wg to global scratch ----
    const float g  = gate[b];
    const float og = 1.0f - g;
#pragma unroll
    for (int k = 0; k < K; ++k) {
        const int i = tid + k * T;
        const float wg = g * (v[k] * inv_sum) + og * last[b * N + i];
        g_wg[b * N + i] = wg;
    }
    __syncthreads();  // global writes by this block visible to this block

    // ---- circular 3-tap shift + sharpening ----
    const float s0 = shift[b * 3 + 0];
    const float s1 = shift[b * 3 + 1];
    const float s2 = shift[b * 3 + 2];
    const float sh = sharpen[b];

    float psum = 0.f;
#pragma unroll
    for (int k = 0; k < K; ++k) {
        const int i   = tid + k * T;
        const int im1 = (i + N - 1) & (N - 1);
        const int ip1 = (i + 1) & (N - 1);
        const float ws = s0 * g_wg[b * N + im1]
                       + s1 * g_wg[b * N + i]
                       + s2 * g_wg[b * N + ip1];
        v[k] = __powf(ws, sh);
        psum += v[k];
    }
#pragma unroll
    for (int o = 16; o > 0; o >>= 1)
        psum += __shfl_xor_sync(0xFFFFFFFFu, psum, o);
    if (lane == 0) red[warp] = psum;
    __syncthreads();
    if (tid < 32) {
        float x = red[tid];
#pragma unroll
        for (int o = 16; o > 0; o >>= 1)
            x += __shfl_xor_sync(0xFFFFFFFFu, x, o);
        if (tid == 0) bc[0] = x;
    }
    __syncthreads();
    const float inv_n = 1.0f / (bc[0] + 1e-16f);

#pragma unroll
    for (int k = 0; k < K; ++k)
        out[b * N + tid + k * T] = v[k] * inv_n;
}

extern "C" void kernel_launch(void* const* d_in, const int* in_sizes, int n_in,
                              void* d_out, int out_size) {
    const float* key     = (const float*)d_in[0];  // [B,M]
    const float* beta    = (const float*)d_in[1];  // [B,1]
    const float* gate    = (const float*)d_in[2];  // [B,1]
    const float* shift   = (const float*)d_in[3];  // [B,3]
    const float* sharpen = (const float*)d_in[4];  // [B,1]
    const float* last    = (const float*)d_in[5];  // [B,N]
    const float* mem     = (const float*)d_in[6];  // [B,N,M]
    float* out = (float*)d_out;

    dim3 g1(N / 64, B);
    k1_logits<<<g1, 256>>>(key, beta, mem);
    k2_address<<<B, 1024>>>(gate, shift, sharpen, last, out);
}